// round 2
// baseline (speedup 1.0000x reference)
#include <cuda_runtime.h>
#include <cuda_bf16.h>

#define BATCH   8
#define NNODES  1024
#define IN_DIM  256
#define OUT_DIM 256
#define HEADS   8
#define HDIM    32
#define ROWS    (BATCH * NNODES)   // 8192
#define M_MAX   256                // max neighbors/row; data is ~5% density (mean 52, sigma 7)

// Scratch (device globals: allocation-free)
__device__ float g_inputs[ROWS * OUT_DIM];       // [B,N,H,D] = X @ W
__device__ float g_self [ROWS * HEADS];          // [B,N,H]
__device__ float g_neigh[ROWS * HEADS];          // [B,N,H]

// ---------------- packed f32x2 helpers ----------------
__device__ __forceinline__ unsigned long long pack2(float lo, float hi) {
    unsigned long long r;
    asm("mov.b64 %0, {%1, %2};" : "=l"(r) : "f"(lo), "f"(hi));
    return r;
}
__device__ __forceinline__ void unpack2(unsigned long long v, float& lo, float& hi) {
    asm("mov.b64 {%0, %1}, %2;" : "=f"(lo), "=f"(hi) : "l"(v));
}
__device__ __forceinline__ unsigned long long fma2(unsigned long long a,
                                                   unsigned long long b,
                                                   unsigned long long c) {
    unsigned long long d;
    asm("fma.rn.f32x2 %0, %1, %2, %3;" : "=l"(d) : "l"(a), "l"(b), "l"(c));
    return d;
}

// ---------------- Kernel 1: inputs = X @ W + fused score projections ----------------
// M=8192, N=256, K=256. BM=64, BN=64, BK=32, 256 threads, 4x4 f32x2/thread,
// double-buffered smem (1 sync per k-tile). Epilogue computes
// self/neigh score partial dots and reduces them within 8-lane octets.
#define BM 64
#define BN 64
#define BK 32

__global__ __launch_bounds__(256)
void gemm_kernel(const float* __restrict__ X, const float* __restrict__ W,
                 float* __restrict__ out,
                 float* __restrict__ self_t, float* __restrict__ neigh_t,
                 const float* __restrict__ fc1, const float* __restrict__ fc2) {
    __shared__ __align__(16) float As[2][BK][BM + 4];  // [k][m]
    __shared__ __align__(16) float Bs[2][BK][BN + 4];  // [k][n]

    const int t  = threadIdx.x;
    const int n0 = blockIdx.x * BN;
    const int m0 = blockIdx.y * BM;
    const int tx = t & 15;
    const int ty = t >> 4;

    unsigned long long acc[4][2];
#pragma unroll
    for (int i = 0; i < 4; i++) { acc[i][0] = 0ull; acc[i][1] = 0ull; }

    // A-tile slot map: s -> (r = s>>3, c = (s&7)<<2); B-tile: (r = s>>4, c = (s&15)<<2)
    const int ar0 = t >> 3,        ac0 = (t & 7) << 2;
    const int ar1 = (t + 256) >> 3, ac1 = ac0;          // (t+256)&7 == t&7
    const int br0 = t >> 4,        bc0 = (t & 15) << 2;
    const int br1 = (t + 256) >> 4, bc1 = bc0;

    // load tile 0 straight to smem
    {
        float4 va0 = *(const float4*)&X[(m0 + ar0) * IN_DIM + ac0];
        float4 va1 = *(const float4*)&X[(m0 + ar1) * IN_DIM + ac1];
        float4 vb0 = *(const float4*)&W[(br0) * OUT_DIM + n0 + bc0];
        float4 vb1 = *(const float4*)&W[(br1) * OUT_DIM + n0 + bc1];
        As[0][ac0 + 0][ar0] = va0.x; As[0][ac0 + 1][ar0] = va0.y;
        As[0][ac0 + 2][ar0] = va0.z; As[0][ac0 + 3][ar0] = va0.w;
        As[0][ac1 + 0][ar1] = va1.x; As[0][ac1 + 1][ar1] = va1.y;
        As[0][ac1 + 2][ar1] = va1.z; As[0][ac1 + 3][ar1] = va1.w;
        *(float4*)&Bs[0][br0][bc0] = vb0;
        *(float4*)&Bs[0][br1][bc1] = vb1;
    }
    __syncthreads();

#pragma unroll
    for (int kt = 0; kt < IN_DIM / BK; kt++) {
        const int cur = kt & 1;
        float4 pa0, pa1, pb0, pb1;
        if (kt < IN_DIM / BK - 1) {
            const int k0 = (kt + 1) * BK;
            pa0 = *(const float4*)&X[(m0 + ar0) * IN_DIM + k0 + ac0];
            pa1 = *(const float4*)&X[(m0 + ar1) * IN_DIM + k0 + ac1];
            pb0 = *(const float4*)&W[(k0 + br0) * OUT_DIM + n0 + bc0];
            pb1 = *(const float4*)&W[(k0 + br1) * OUT_DIM + n0 + bc1];
        }
#pragma unroll
        for (int k = 0; k < BK; k++) {
            float4 a = *(const float4*)&As[cur][k][ty * 4];
            float4 b = *(const float4*)&Bs[cur][k][tx * 4];
            unsigned long long b01 = pack2(b.x, b.y);
            unsigned long long b23 = pack2(b.z, b.w);
            unsigned long long a2;
            a2 = pack2(a.x, a.x); acc[0][0] = fma2(a2, b01, acc[0][0]); acc[0][1] = fma2(a2, b23, acc[0][1]);
            a2 = pack2(a.y, a.y); acc[1][0] = fma2(a2, b01, acc[1][0]); acc[1][1] = fma2(a2, b23, acc[1][1]);
            a2 = pack2(a.z, a.z); acc[2][0] = fma2(a2, b01, acc[2][0]); acc[2][1] = fma2(a2, b23, acc[2][1]);
            a2 = pack2(a.w, a.w); acc[3][0] = fma2(a2, b01, acc[3][0]); acc[3][1] = fma2(a2, b23, acc[3][1]);
        }
        if (kt < IN_DIM / BK - 1) {
            const int nxt = cur ^ 1;
            As[nxt][ac0 + 0][ar0] = pa0.x; As[nxt][ac0 + 1][ar0] = pa0.y;
            As[nxt][ac0 + 2][ar0] = pa0.z; As[nxt][ac0 + 3][ar0] = pa0.w;
            As[nxt][ac1 + 0][ar1] = pa1.x; As[nxt][ac1 + 1][ar1] = pa1.y;
            As[nxt][ac1 + 2][ar1] = pa1.z; As[nxt][ac1 + 3][ar1] = pa1.w;
            *(float4*)&Bs[nxt][br0][bc0] = pb0;
            *(float4*)&Bs[nxt][br1][bc1] = pb1;
            __syncthreads();
        }
    }

    // epilogue: store out tile + fused score projections
    const int col = n0 + tx * 4;
    const int h   = col >> 5;
    const int dd  = col & 31;
    const float f1x = fc1[h * HDIM + dd],     f1y = fc1[h * HDIM + dd + 1];
    const float f1z = fc1[h * HDIM + dd + 2], f1w = fc1[h * HDIM + dd + 3];
    const float f2x = fc2[h * HDIM + dd],     f2y = fc2[h * HDIM + dd + 1];
    const float f2z = fc2[h * HDIM + dd + 2], f2w = fc2[h * HDIM + dd + 3];

#pragma unroll
    for (int i = 0; i < 4; i++) {
        const int row = m0 + ty * 4 + i;
        float4 o;
        unpack2(acc[i][0], o.x, o.y);
        unpack2(acc[i][1], o.z, o.w);
        *(float4*)&out[row * OUT_DIM + col] = o;

        float s1 = o.x * f1x + o.y * f1y + o.z * f1z + o.w * f1w;
        float s2 = o.x * f2x + o.y * f2y + o.z * f2z + o.w * f2w;
#pragma unroll
        for (int off = 1; off < 8; off <<= 1) {
            s1 += __shfl_xor_sync(0xffffffffu, s1, off);
            s2 += __shfl_xor_sync(0xffffffffu, s2, off);
        }
        if ((tx & 7) == 0) {            // tx==0 (head h_base) and tx==8 (head h_base+1)
            self_t [row * HEADS + h] = s1;
            neigh_t[row * HEADS + h] = s2;
        }
    }
}

// ---------------- Kernel 2: sparse softmax + aggregation + relu ----------------
// One block per (b, n). exp(-1e9) underflows to 0 in fp32 so the dense-masked
// softmax equals the softmax over A's nonzeros (self-loop always present).
__global__ __launch_bounds__(256)
void attn_kernel(const float* __restrict__ A,
                 const float* __restrict__ inp,
                 const float* __restrict__ self_t, const float* __restrict__ neigh_t,
                 float* __restrict__ out) {
    __shared__ float  sc[HEADS][M_MAX];     // 8 KB: scores then exp-scores [h][j]
    __shared__ int    nbr[M_MAX];
    __shared__ float  s_self[HEADS];
    __shared__ float  s_inv[HEADS];
    __shared__ float4 red[4][64];           // 4 KB
    __shared__ int    s_cnt;

    const int blk = blockIdx.x;
    const int b = blk >> 10;
    const int t = threadIdx.x;

    if (t == 0) s_cnt = 0;
    if (t < HEADS) s_self[t] = self_t[blk * HEADS + t];
    __syncthreads();

    // Phase 1: compact nonzero columns of A[b,n,:]  (each thread: one float4)
    {
        const float4 v = ((const float4*)(A + (long)blk * NNODES))[t];
        int idx[4]; int c = 0;
        if (v.x != 0.0f) idx[c++] = 4 * t + 0;
        if (v.y != 0.0f) idx[c++] = 4 * t + 1;
        if (v.z != 0.0f) idx[c++] = 4 * t + 2;
        if (v.w != 0.0f) idx[c++] = 4 * t + 3;
        if (c) {
            int p = atomicAdd(&s_cnt, c);
            for (int i = 0; i < c; i++) nbr[p + i] = idx[i];
        }
    }
    __syncthreads();
    const int M = s_cnt;

    // Phase 2a: sc[h][j] = leaky_relu(self[h] + neigh[nbr[j]][h])
    // thread -> (j = t>>3, h = t&7): 8 threads share a 32B neigh sector.
    {
        const float* nb = neigh_t + (long)b * NNODES * HEADS;
        const int hh = t & 7;
        for (int j = t >> 3; j < M; j += 32) {
            float s = s_self[hh] + nb[nbr[j] * HEADS + hh];
            sc[hh][j] = (s > 0.0f) ? s : 0.01f * s;
        }
    }
    __syncthreads();

    // Phase 2b: per-head max/exp/sum (warp w owns head w; conflict-free rows)
    {
        const int w = t >> 5, lane = t & 31;
        float mx = -1e30f;
        for (int j = lane; j < M; j += 32) mx = fmaxf(mx, sc[w][j]);
#pragma unroll
        for (int o = 16; o > 0; o >>= 1) mx = fmaxf(mx, __shfl_xor_sync(0xffffffffu, mx, o));
        float sum = 0.0f;
        for (int j = lane; j < M; j += 32) {
            float e = __expf(sc[w][j] - mx);
            sc[w][j] = e;
            sum += e;
        }
#pragma unroll
        for (int o = 16; o > 0; o >>= 1) sum += __shfl_xor_sync(0xffffffffu, sum, o);
        if (lane == 0) s_inv[w] = 1.0f / sum;
    }
    __syncthreads();

    // Phase 3: float4 gather-aggregate. 64 threads cover a 1KB row; 4 neighbor
    // groups run in parallel, then reduce through smem.
    {
        const int g = t >> 6;          // neighbor subgroup 0..3
        const int c = t & 63;          // float4 column
        const int hh = c >> 3;
        const float* inpb = inp + (long)b * NNODES * OUT_DIM;
        float4 a0 = make_float4(0.f, 0.f, 0.f, 0.f);
        float4 a1 = make_float4(0.f, 0.f, 0.f, 0.f);
        int j = g;
        for (; j + 4 < M; j += 8) {
            const int i0 = nbr[j], i1 = nbr[j + 4];
            const float w0 = sc[hh][j], w1 = sc[hh][j + 4];
            const float4 v0 = *(const float4*)&inpb[i0 * OUT_DIM + c * 4];
            const float4 v1 = *(const float4*)&inpb[i1 * OUT_DIM + c * 4];
            a0.x += w0 * v0.x; a0.y += w0 * v0.y; a0.z += w0 * v0.z; a0.w += w0 * v0.w;
            a1.x += w1 * v1.x; a1.y += w1 * v1.y; a1.z += w1 * v1.z; a1.w += w1 * v1.w;
        }
        for (; j < M; j += 4) {
            const int i0 = nbr[j];
            const float w0 = sc[hh][j];
            const float4 v0 = *(const float4*)&inpb[i0 * OUT_DIM + c * 4];
            a0.x += w0 * v0.x; a0.y += w0 * v0.y; a0.z += w0 * v0.z; a0.w += w0 * v0.w;
        }
        a0.x += a1.x; a0.y += a1.y; a0.z += a1.z; a0.w += a1.w;
        red[g][c] = a0;
    }
    __syncthreads();
    if (t < 64) {
        const float4 r0 = red[0][t], r1 = red[1][t], r2 = red[2][t], r3 = red[3][t];
        const float inv = s_inv[t >> 3];
        float4 o;
        o.x = fmaxf((r0.x + r1.x + r2.x + r3.x) * inv, 0.0f);
        o.y = fmaxf((r0.y + r1.y + r2.y + r3.y) * inv, 0.0f);
        o.z = fmaxf((r0.z + r1.z + r2.z + r3.z) * inv, 0.0f);
        o.w = fmaxf((r0.w + r1.w + r2.w + r3.w) * inv, 0.0f);
        *(float4*)&out[(long)blk * OUT_DIM + t * 4] = o;
    }
}

// ---------------- launch ----------------
extern "C" void kernel_launch(void* const* d_in, const int* in_sizes, int n_in,
                              void* d_out, int out_size) {
    const float* A   = (const float*)d_in[0];
    const float* X   = (const float*)d_in[1];
    const float* W   = (const float*)d_in[2];
    const float* fc1 = (const float*)d_in[3];
    const float* fc2 = (const float*)d_in[4];
    float* out = (float*)d_out;

    float* inp;     cudaGetSymbolAddress((void**)&inp,    g_inputs);
    float* self_t;  cudaGetSymbolAddress((void**)&self_t, g_self);
    float* neigh_t; cudaGetSymbolAddress((void**)&neigh_t, g_neigh);

    dim3 ggrid(OUT_DIM / BN, ROWS / BM);   // (4, 128)
    gemm_kernel<<<ggrid, 256>>>(X, W, inp, self_t, neigh_t, fc1, fc2);
    attn_kernel<<<ROWS, 256>>>(A, inp, self_t, neigh_t, out);
}

// round 4
// speedup vs baseline: 1.5427x; 1.5427x over previous
#include <cuda_runtime.h>
#include <cuda_bf16.h>

#define BATCH   8
#define NNODES  1024
#define IN_DIM  256
#define OUT_DIM 256
#define HEADS   8
#define HDIM    32
#define ROWS    (BATCH * NNODES)   // 8192
#define M_MAX   256                // max neighbors/row (~5% density => mean ~52)

// Scratch (device globals: allocation-free)
__device__ float g_inputs[ROWS * OUT_DIM];   // [B,N,H,D] = X @ W (fp32)
__device__ float g_self [ROWS * HEADS];      // [B,N,H]
__device__ float g_neigh[ROWS * HEADS];      // [B,N,H]

// ---------------- packed f32x2 helpers ----------------
__device__ __forceinline__ unsigned long long pack2(float lo, float hi) {
    unsigned long long r;
    asm("mov.b64 %0, {%1, %2};" : "=l"(r) : "f"(lo), "f"(hi));
    return r;
}
__device__ __forceinline__ void unpack2(unsigned long long v, float& lo, float& hi) {
    asm("mov.b64 {%0, %1}, %2;" : "=f"(lo), "=f"(hi) : "l"(v));
}
__device__ __forceinline__ unsigned long long fma2(unsigned long long a,
                                                   unsigned long long b,
                                                   unsigned long long c) {
    unsigned long long d;
    asm("fma.rn.f32x2 %0, %1, %2, %3;" : "=l"(d) : "l"(a), "l"(b), "l"(c));
    return d;
}

// ---------------- Kernel 1: inputs = X @ W, fused score projections ----------------
// R1 single-buffer mainloop (known-good). Epilogue: fp32 store + self/neigh
// rank-1 score dots reduced within 8-lane octets.
#define BM 64
#define BN 64
#define BK 32

__global__ __launch_bounds__(256)
void gemm_kernel(const float* __restrict__ X, const float* __restrict__ W,
                 float* __restrict__ out,
                 float* __restrict__ self_t, float* __restrict__ neigh_t,
                 const float* __restrict__ fc1, const float* __restrict__ fc2) {
    __shared__ __align__(16) float As[BK][BM + 4];  // [k][m]
    __shared__ __align__(16) float Bs[BK][BN + 4];  // [k][n]

    const int t  = threadIdx.x;
    const int n0 = blockIdx.x * BN;
    const int m0 = blockIdx.y * BM;
    const int tx = t & 15;
    const int ty = t >> 4;

    unsigned long long acc[4][2];
#pragma unroll
    for (int i = 0; i < 4; i++) { acc[i][0] = 0ull; acc[i][1] = 0ull; }

    for (int k0 = 0; k0 < IN_DIM; k0 += BK) {
#pragma unroll
        for (int s = t; s < 512; s += 256) {
            int r = s >> 3;
            int c = (s & 7) << 2;
            float4 v = *(const float4*)&X[(m0 + r) * IN_DIM + k0 + c];
            As[c + 0][r] = v.x; As[c + 1][r] = v.y;
            As[c + 2][r] = v.z; As[c + 3][r] = v.w;
        }
#pragma unroll
        for (int s = t; s < 512; s += 256) {
            int r = s >> 4;
            int c = (s & 15) << 2;
            *(float4*)&Bs[r][c] = *(const float4*)&W[(k0 + r) * OUT_DIM + n0 + c];
        }
        __syncthreads();

#pragma unroll
        for (int k = 0; k < BK; k++) {
            float4 a = *(const float4*)&As[k][ty * 4];
            float4 b = *(const float4*)&Bs[k][tx * 4];
            unsigned long long b01 = pack2(b.x, b.y);
            unsigned long long b23 = pack2(b.z, b.w);
            unsigned long long a2;
            a2 = pack2(a.x, a.x); acc[0][0] = fma2(a2, b01, acc[0][0]); acc[0][1] = fma2(a2, b23, acc[0][1]);
            a2 = pack2(a.y, a.y); acc[1][0] = fma2(a2, b01, acc[1][0]); acc[1][1] = fma2(a2, b23, acc[1][1]);
            a2 = pack2(a.z, a.z); acc[2][0] = fma2(a2, b01, acc[2][0]); acc[2][1] = fma2(a2, b23, acc[2][1]);
            a2 = pack2(a.w, a.w); acc[3][0] = fma2(a2, b01, acc[3][0]); acc[3][1] = fma2(a2, b23, acc[3][1]);
        }
        __syncthreads();
    }

    // ---- epilogue: fp32 store + fused score projections ----
    const int col = n0 + tx * 4;
    const int h   = col >> 5;
    const int dd  = col & 31;
    const float f1x = fc1[h * HDIM + dd],     f1y = fc1[h * HDIM + dd + 1];
    const float f1z = fc1[h * HDIM + dd + 2], f1w = fc1[h * HDIM + dd + 3];
    const float f2x = fc2[h * HDIM + dd],     f2y = fc2[h * HDIM + dd + 1];
    const float f2z = fc2[h * HDIM + dd + 2], f2w = fc2[h * HDIM + dd + 3];

#pragma unroll
    for (int i = 0; i < 4; i++) {
        const int row = m0 + ty * 4 + i;
        float4 o;
        unpack2(acc[i][0], o.x, o.y);
        unpack2(acc[i][1], o.z, o.w);
        *(float4*)&out[row * OUT_DIM + col] = o;

        float s1 = o.x * f1x + o.y * f1y + o.z * f1z + o.w * f1w;
        float s2 = o.x * f2x + o.y * f2y + o.z * f2z + o.w * f2w;
#pragma unroll
        for (int off = 1; off < 8; off <<= 1) {
            s1 += __shfl_xor_sync(0xffffffffu, s1, off);
            s2 += __shfl_xor_sync(0xffffffffu, s2, off);
        }
        if ((tx & 7) == 0) {
            self_t [row * HEADS + h] = s1;
            neigh_t[row * HEADS + h] = s2;
        }
    }
}

// ---------------- Kernel 2: sparse softmax + aggregation + relu ----------------
// One block per (b,n). exp(-1e9) underflows to 0 in fp32 so the dense-masked
// softmax equals the softmax over A's nonzeros (self-loop always present).
__global__ __launch_bounds__(256)
void attn_kernel(const float* __restrict__ A,
                 const float* __restrict__ inp,
                 const float* __restrict__ self_t, const float* __restrict__ neigh_t,
                 float* __restrict__ out) {
    __shared__ float  sc[HEADS][M_MAX];     // 8 KB, [h][j] (conflict-free warp rows)
    __shared__ int    nbr[M_MAX];
    __shared__ float  s_self[HEADS];
    __shared__ float  s_inv[HEADS];
    __shared__ float2 red[2][128];          // 2 KB
    __shared__ int    s_cnt;

    const int blk = blockIdx.x;
    const int b = blk >> 10;
    const int t = threadIdx.x;

    if (t == 0) s_cnt = 0;
    if (t < HEADS) s_self[t] = self_t[blk * HEADS + t];
    __syncthreads();

    // Phase 1: compact nonzero columns of A[b,n,:] (one float4 per thread)
    {
        const float4 v = ((const float4*)(A + (long)blk * NNODES))[t];
        int idx[4]; int c = 0;
        if (v.x != 0.0f) idx[c++] = 4 * t + 0;
        if (v.y != 0.0f) idx[c++] = 4 * t + 1;
        if (v.z != 0.0f) idx[c++] = 4 * t + 2;
        if (v.w != 0.0f) idx[c++] = 4 * t + 3;
        if (c) {
            int p = atomicAdd(&s_cnt, c);
            for (int i = 0; i < c; i++) nbr[p + i] = idx[i];
        }
    }
    __syncthreads();
    const int M = s_cnt;

    // Phase 2: warp w owns head w. Leaky scores + running max in one pass,
    // then exp+sum pass. Warp-local; one sync after.
    {
        const int w = t >> 5, lane = t & 31;
        const float* nb = neigh_t + (long)b * NNODES * HEADS;
        const float sw = s_self[w];
        float mx = -1e30f;
        for (int j = lane; j < M; j += 32) {
            float s = sw + nb[nbr[j] * HEADS + w];
            s = (s > 0.0f) ? s : 0.01f * s;
            sc[w][j] = s;
            mx = fmaxf(mx, s);
        }
#pragma unroll
        for (int o = 16; o > 0; o >>= 1) mx = fmaxf(mx, __shfl_xor_sync(0xffffffffu, mx, o));
        float sum = 0.0f;
        for (int j = lane; j < M; j += 32) {
            float e = __expf(sc[w][j] - mx);
            sc[w][j] = e;
            sum += e;
        }
#pragma unroll
        for (int o = 16; o > 0; o >>= 1) sum += __shfl_xor_sync(0xffffffffu, sum, o);
        if (lane == 0) s_inv[w] = 1.0f / sum;
    }
    __syncthreads();

    // Phase 3: fp32 float2 gather-aggregate. 128 threads cover a 1KB row,
    // 2 neighbor groups, 4-deep unroll (MLP=4), fp32 accumulate.
    {
        const int g = t >> 7;            // neighbor subgroup 0..1
        const int c = t & 127;           // float2 column (dims 2c, 2c+1)
        const int h = c >> 4;
        const float2* inpb = (const float2*)inp + (long)b * NNODES * (OUT_DIM / 2);
        float2 a0 = make_float2(0.f, 0.f), a1 = make_float2(0.f, 0.f);
        float2 a2 = make_float2(0.f, 0.f), a3 = make_float2(0.f, 0.f);
        int j = g;
        for (; j + 6 < M; j += 8) {
            const int i0 = nbr[j], i1 = nbr[j + 2], i2 = nbr[j + 4], i3 = nbr[j + 6];
            const float w0 = sc[h][j],     w1 = sc[h][j + 2];
            const float w2 = sc[h][j + 4], w3 = sc[h][j + 6];
            const float2 v0 = inpb[i0 * 128 + c];
            const float2 v1 = inpb[i1 * 128 + c];
            const float2 v2 = inpb[i2 * 128 + c];
            const float2 v3 = inpb[i3 * 128 + c];
            a0.x += w0 * v0.x; a0.y += w0 * v0.y;
            a1.x += w1 * v1.x; a1.y += w1 * v1.y;
            a2.x += w2 * v2.x; a2.y += w2 * v2.y;
            a3.x += w3 * v3.x; a3.y += w3 * v3.y;
        }
        for (; j < M; j += 2) {
            const int i0 = nbr[j];
            const float w0 = sc[h][j];
            const float2 v0 = inpb[i0 * 128 + c];
            a0.x += w0 * v0.x; a0.y += w0 * v0.y;
        }
        a0.x = (a0.x + a1.x) + (a2.x + a3.x);
        a0.y = (a0.y + a1.y) + (a2.y + a3.y);
        red[g][c] = a0;
    }
    __syncthreads();
    if (t < 128) {
        const float2 r0 = red[0][t], r1 = red[1][t];
        const float inv = s_inv[t >> 4];
        float2 o;
        o.x = fmaxf((r0.x + r1.x) * inv, 0.0f);
        o.y = fmaxf((r0.y + r1.y) * inv, 0.0f);
        *(float2*)&out[(long)blk * OUT_DIM + t * 2] = o;
    }
}

// ---------------- launch ----------------
extern "C" void kernel_launch(void* const* d_in, const int* in_sizes, int n_in,
                              void* d_out, int out_size) {
    const float* A   = (const float*)d_in[0];
    const float* X   = (const float*)d_in[1];
    const float* W   = (const float*)d_in[2];
    const float* fc1 = (const float*)d_in[3];
    const float* fc2 = (const float*)d_in[4];
    float* out = (float*)d_out;

    float *inp, *self_t, *neigh_t;
    cudaGetSymbolAddress((void**)&inp,     g_inputs);
    cudaGetSymbolAddress((void**)&self_t,  g_self);
    cudaGetSymbolAddress((void**)&neigh_t, g_neigh);

    dim3 ggrid(OUT_DIM / BN, ROWS / BM);   // (4, 128)
    gemm_kernel<<<ggrid, 256>>>(X, W, inp, self_t, neigh_t, fc1, fc2);
    attn_kernel<<<ROWS, 256>>>(A, inp, self_t, neigh_t, out);
}

// round 6
// speedup vs baseline: 1.5433x; 1.0004x over previous
#include <cuda_runtime.h>
#include <cuda_bf16.h>

#define BATCH   8
#define NNODES  1024
#define IN_DIM  256
#define OUT_DIM 256
#define HEADS   8
#define HDIM    32
#define ROWS    (BATCH * NNODES)   // 8192
#define M_MAX   256                // max neighbors/row (~5% density => mean ~52)
#define SC_STR  264                // score row stride: 264%32=8 -> conflict-free h-reads

// Scratch (device globals: allocation-free)
__device__ float g_inputs[ROWS * OUT_DIM];   // [B,N,H,D] = X @ W (fp32)
__device__ float g_self [ROWS * HEADS];      // [B,N,H]
__device__ float g_neigh[ROWS * HEADS];      // [B,N,H]

// ---------------- packed f32x2 helpers ----------------
__device__ __forceinline__ unsigned long long pack2(float lo, float hi) {
    unsigned long long r;
    asm("mov.b64 %0, {%1, %2};" : "=l"(r) : "f"(lo), "f"(hi));
    return r;
}
__device__ __forceinline__ void unpack2(unsigned long long v, float& lo, float& hi) {
    asm("mov.b64 {%0, %1}, %2;" : "=f"(lo), "=f"(hi) : "l"(v));
}
__device__ __forceinline__ unsigned long long fma2(unsigned long long a,
                                                   unsigned long long b,
                                                   unsigned long long c) {
    unsigned long long d;
    asm("fma.rn.f32x2 %0, %1, %2, %3;" : "=l"(d) : "l"(a), "l"(b), "l"(c));
    return d;
}

// ---------------- Kernel 1: inputs = X @ W, fused score projections ----------------
// (unchanged from R4 — known-good)
#define BM 64
#define BN 64
#define BK 32

__global__ __launch_bounds__(256)
void gemm_kernel(const float* __restrict__ X, const float* __restrict__ W,
                 float* __restrict__ out,
                 float* __restrict__ self_t, float* __restrict__ neigh_t,
                 const float* __restrict__ fc1, const float* __restrict__ fc2) {
    __shared__ __align__(16) float As[BK][BM + 4];  // [k][m]
    __shared__ __align__(16) float Bs[BK][BN + 4];  // [k][n]

    const int t  = threadIdx.x;
    const int n0 = blockIdx.x * BN;
    const int m0 = blockIdx.y * BM;
    const int tx = t & 15;
    const int ty = t >> 4;

    unsigned long long acc[4][2];
#pragma unroll
    for (int i = 0; i < 4; i++) { acc[i][0] = 0ull; acc[i][1] = 0ull; }

    for (int k0 = 0; k0 < IN_DIM; k0 += BK) {
#pragma unroll
        for (int s = t; s < 512; s += 256) {
            int r = s >> 3;
            int c = (s & 7) << 2;
            float4 v = *(const float4*)&X[(m0 + r) * IN_DIM + k0 + c];
            As[c + 0][r] = v.x; As[c + 1][r] = v.y;
            As[c + 2][r] = v.z; As[c + 3][r] = v.w;
        }
#pragma unroll
        for (int s = t; s < 512; s += 256) {
            int r = s >> 4;
            int c = (s & 15) << 2;
            *(float4*)&Bs[r][c] = *(const float4*)&W[(k0 + r) * OUT_DIM + n0 + c];
        }
        __syncthreads();

#pragma unroll
        for (int k = 0; k < BK; k++) {
            float4 a = *(const float4*)&As[k][ty * 4];
            float4 b = *(const float4*)&Bs[k][tx * 4];
            unsigned long long b01 = pack2(b.x, b.y);
            unsigned long long b23 = pack2(b.z, b.w);
            unsigned long long a2;
            a2 = pack2(a.x, a.x); acc[0][0] = fma2(a2, b01, acc[0][0]); acc[0][1] = fma2(a2, b23, acc[0][1]);
            a2 = pack2(a.y, a.y); acc[1][0] = fma2(a2, b01, acc[1][0]); acc[1][1] = fma2(a2, b23, acc[1][1]);
            a2 = pack2(a.z, a.z); acc[2][0] = fma2(a2, b01, acc[2][0]); acc[2][1] = fma2(a2, b23, acc[2][1]);
            a2 = pack2(a.w, a.w); acc[3][0] = fma2(a2, b01, acc[3][0]); acc[3][1] = fma2(a2, b23, acc[3][1]);
        }
        __syncthreads();
    }

    const int col = n0 + tx * 4;
    const int h   = col >> 5;
    const int dd  = col & 31;
    const float f1x = fc1[h * HDIM + dd],     f1y = fc1[h * HDIM + dd + 1];
    const float f1z = fc1[h * HDIM + dd + 2], f1w = fc1[h * HDIM + dd + 3];
    const float f2x = fc2[h * HDIM + dd],     f2y = fc2[h * HDIM + dd + 1];
    const float f2z = fc2[h * HDIM + dd + 2], f2w = fc2[h * HDIM + dd + 3];

#pragma unroll
    for (int i = 0; i < 4; i++) {
        const int row = m0 + ty * 4 + i;
        float4 o;
        unpack2(acc[i][0], o.x, o.y);
        unpack2(acc[i][1], o.z, o.w);
        *(float4*)&out[row * OUT_DIM + col] = o;

        float s1 = o.x * f1x + o.y * f1y + o.z * f1z + o.w * f1w;
        float s2 = o.x * f2x + o.y * f2y + o.z * f2z + o.w * f2w;
#pragma unroll
        for (int off = 1; off < 8; off <<= 1) {
            s1 += __shfl_xor_sync(0xffffffffu, s1, off);
            s2 += __shfl_xor_sync(0xffffffffu, s2, off);
        }
        if ((tx & 7) == 0) {
            self_t [row * HEADS + h] = s1;
            neigh_t[row * HEADS + h] = s2;
        }
    }
}

// ---------------- Kernel 2: sparse softmax + aggregation + relu ----------------
__global__ __launch_bounds__(256)
void attn_kernel(const float* __restrict__ A,
                 const float* __restrict__ inp,
                 const float* __restrict__ self_t, const float* __restrict__ neigh_t,
                 float* __restrict__ out) {
    __shared__ float  sc[HEADS][SC_STR];    // exp-scores, padded stride
    __shared__ int    nbr[M_MAX];           // neighbor index * 64 (float4 row stride)
    __shared__ float  s_self[HEADS];
    __shared__ float  s_inv[HEADS];
    __shared__ float4 red[4][64];           // 4 KB cross-group reduction
    __shared__ int    s_cnt;

    const int blk = blockIdx.x;
    const int b = blk >> 10;
    const int t = threadIdx.x;

    if (t == 0) s_cnt = 0;
    if (t < HEADS) s_self[t] = self_t[blk * HEADS + t];
    __syncthreads();

    // Phase 1: compact nonzero columns of A[b,n,:]; store idx*64 (float4 units)
    {
        const float4 v = ((const float4*)(A + (long)blk * NNODES))[t];
        int idx[4]; int c = 0;
        if (v.x != 0.0f) idx[c++] = (4 * t + 0) << 6;
        if (v.y != 0.0f) idx[c++] = (4 * t + 1) << 6;
        if (v.z != 0.0f) idx[c++] = (4 * t + 2) << 6;
        if (v.w != 0.0f) idx[c++] = (4 * t + 3) << 6;
        if (c) {
            int p = atomicAdd(&s_cnt, c);
            for (int i = 0; i < c; i++) nbr[p + i] = idx[i];
        }
    }
    __syncthreads();
    const int M = s_cnt;

    // Phase 2: warp w owns head w. Leaky scores + running max, then exp+sum.
    {
        const int w = t >> 5, lane = t & 31;
        const float* nb = neigh_t + (long)b * NNODES * HEADS;
        const float sw = s_self[w];
        float mx = -1e30f;
        for (int j = lane; j < M; j += 32) {
            float s = sw + nb[(nbr[j] >> 3) + w];   // idx*64>>3 == idx*HEADS
            s = (s > 0.0f) ? s : 0.01f * s;
            sc[w][j] = s;
            mx = fmaxf(mx, s);
        }
#pragma unroll
        for (int o = 16; o > 0; o >>= 1) mx = fmaxf(mx, __shfl_xor_sync(0xffffffffu, mx, o));
        float sum = 0.0f;
        for (int j = lane; j < M; j += 32) {
            float e = __expf(sc[w][j] - mx);
            sc[w][j] = e;
            sum += e;
        }
#pragma unroll
        for (int o = 16; o > 0; o >>= 1) sum += __shfl_xor_sync(0xffffffffu, sum, o);
        if (lane == 0) s_inv[w] = 1.0f / sum;
    }
    __syncthreads();

    // Phase 3: float4 gather-aggregate. 64 threads cover a 1KB row; 4 neighbor
    // subgroups; 4 loads in flight per thread (MLP=4).
    {
        const int g = t >> 6;          // subgroup 0..3
        const int c = t & 63;          // float4 column
        const int h = c >> 3;
        const float4* inpb = (const float4*)inp + (long)b * NNODES * (OUT_DIM / 4);
        float4 a0 = make_float4(0.f, 0.f, 0.f, 0.f);
        float4 a1 = make_float4(0.f, 0.f, 0.f, 0.f);
        float4 a2 = make_float4(0.f, 0.f, 0.f, 0.f);
        float4 a3 = make_float4(0.f, 0.f, 0.f, 0.f);
        int j = g;
        for (; j + 12 < M; j += 16) {
            const int i0 = nbr[j], i1 = nbr[j + 4], i2 = nbr[j + 8], i3 = nbr[j + 12];
            const float w0 = sc[h][j],     w1 = sc[h][j + 4];
            const float w2 = sc[h][j + 8], w3 = sc[h][j + 12];
            const float4 v0 = inpb[i0 + c];
            const float4 v1 = inpb[i1 + c];
            const float4 v2 = inpb[i2 + c];
            const float4 v3 = inpb[i3 + c];
            a0.x += w0 * v0.x; a0.y += w0 * v0.y; a0.z += w0 * v0.z; a0.w += w0 * v0.w;
            a1.x += w1 * v1.x; a1.y += w1 * v1.y; a1.z += w1 * v1.z; a1.w += w1 * v1.w;
            a2.x += w2 * v2.x; a2.y += w2 * v2.y; a2.z += w2 * v2.z; a2.w += w2 * v2.w;
            a3.x += w3 * v3.x; a3.y += w3 * v3.y; a3.z += w3 * v3.z; a3.w += w3 * v3.w;
        }
        for (; j < M; j += 4) {
            const int i0 = nbr[j];
            const float w0 = sc[h][j];
            const float4 v0 = inpb[i0 + c];
            a0.x += w0 * v0.x; a0.y += w0 * v0.y; a0.z += w0 * v0.z; a0.w += w0 * v0.w;
        }
        a0.x = (a0.x + a1.x) + (a2.x + a3.x);
        a0.y = (a0.y + a1.y) + (a2.y + a3.y);
        a0.z = (a0.z + a1.z) + (a2.z + a3.z);
        a0.w = (a0.w + a1.w) + (a2.w + a3.w);
        red[g][c] = a0;
    }
    __syncthreads();
    if (t < 64) {
        const float4 r0 = red[0][t], r1 = red[1][t], r2 = red[2][t], r3 = red[3][t];
        const float inv = s_inv[t >> 3];
        float4 o;
        o.x = fmaxf((r0.x + r1.x + r2.x + r3.x) * inv, 0.0f);
        o.y = fmaxf((r0.y + r1.y + r2.y + r3.y) * inv, 0.0f);
        o.z = fmaxf((r0.z + r1.z + r2.z + r3.z) * inv, 0.0f);
        o.w = fmaxf((r0.w + r1.w + r2.w + r3.w) * inv, 0.0f);
        *(float4*)&out[(long)blk * OUT_DIM + t * 4] = o;
    }
}

// ---------------- launch ----------------
extern "C" void kernel_launch(void* const* d_in, const int* in_sizes, int n_in,
                              void* d_out, int out_size) {
    const float* A   = (const float*)d_in[0];
    const float* X   = (const float*)d_in[1];
    const float* W   = (const float*)d_in[2];
    const float* fc1 = (const float*)d_in[3];
    const float* fc2 = (const float*)d_in[4];
    float* out = (float*)d_out;

    float *inp, *self_t, *neigh_t;
    cudaGetSymbolAddress((void**)&inp,     g_inputs);
    cudaGetSymbolAddress((void**)&self_t,  g_self);
    cudaGetSymbolAddress((void**)&neigh_t, g_neigh);

    dim3 ggrid(OUT_DIM / BN, ROWS / BM);   // (4, 128)
    gemm_kernel<<<ggrid, 256>>>(X, W, inp, self_t, neigh_t, fc1, fc2);
    attn_kernel<<<ROWS, 256>>>(A, inp, self_t, neigh_t, out);
}

// round 10
// speedup vs baseline: 1.6164x; 1.0474x over previous
#include <cuda_runtime.h>
#include <cuda_bf16.h>

#define BATCH   8
#define NNODES  1024
#define IN_DIM  256
#define OUT_DIM 256
#define HEADS   8
#define HDIM    32
#define ROWS    (BATCH * NNODES)   // 8192
#define RPB     4                  // rows per attn block
#define M_MAX   160                // max neighbors/row (mean ~52, sd ~7; 160 = 15 sd)
#define SC_STR  161                // odd stride -> conflict-free per-head broadcast reads

// Scratch (device globals: allocation-free)
__device__ float g_inputs[ROWS * OUT_DIM];   // [B,N,H,D] = X @ W (fp32)
__device__ float g_self [ROWS * HEADS];      // [B,N,H]
__device__ float g_neigh[ROWS * HEADS];      // [B,N,H]

// ---------------- packed f32x2 helpers ----------------
__device__ __forceinline__ unsigned long long pack2(float lo, float hi) {
    unsigned long long r;
    asm("mov.b64 %0, {%1, %2};" : "=l"(r) : "f"(lo), "f"(hi));
    return r;
}
__device__ __forceinline__ void unpack2(unsigned long long v, float& lo, float& hi) {
    asm("mov.b64 {%0, %1}, %2;" : "=f"(lo), "=f"(hi) : "l"(v));
}
__device__ __forceinline__ unsigned long long fma2(unsigned long long a,
                                                   unsigned long long b,
                                                   unsigned long long c) {
    unsigned long long d;
    asm("fma.rn.f32x2 %0, %1, %2, %3;" : "=l"(d) : "l"(a), "l"(b), "l"(c));
    return d;
}

// ---------------- Kernel 1: inputs = X @ W, fused score projections ----------------
// (unchanged — known-good, ~35 us)
#define BM 64
#define BN 64
#define BK 32

__global__ __launch_bounds__(256)
void gemm_kernel(const float* __restrict__ X, const float* __restrict__ W,
                 float* __restrict__ out,
                 float* __restrict__ self_t, float* __restrict__ neigh_t,
                 const float* __restrict__ fc1, const float* __restrict__ fc2) {
    __shared__ __align__(16) float As[BK][BM + 4];
    __shared__ __align__(16) float Bs[BK][BN + 4];

    const int t  = threadIdx.x;
    const int n0 = blockIdx.x * BN;
    const int m0 = blockIdx.y * BM;
    const int tx = t & 15;
    const int ty = t >> 4;

    unsigned long long acc[4][2];
#pragma unroll
    for (int i = 0; i < 4; i++) { acc[i][0] = 0ull; acc[i][1] = 0ull; }

    for (int k0 = 0; k0 < IN_DIM; k0 += BK) {
#pragma unroll
        for (int s = t; s < 512; s += 256) {
            int r = s >> 3;
            int c = (s & 7) << 2;
            float4 v = *(const float4*)&X[(m0 + r) * IN_DIM + k0 + c];
            As[c + 0][r] = v.x; As[c + 1][r] = v.y;
            As[c + 2][r] = v.z; As[c + 3][r] = v.w;
        }
#pragma unroll
        for (int s = t; s < 512; s += 256) {
            int r = s >> 4;
            int c = (s & 15) << 2;
            *(float4*)&Bs[r][c] = *(const float4*)&W[(k0 + r) * OUT_DIM + n0 + c];
        }
        __syncthreads();

#pragma unroll
        for (int k = 0; k < BK; k++) {
            float4 a = *(const float4*)&As[k][ty * 4];
            float4 b = *(const float4*)&Bs[k][tx * 4];
            unsigned long long b01 = pack2(b.x, b.y);
            unsigned long long b23 = pack2(b.z, b.w);
            unsigned long long a2;
            a2 = pack2(a.x, a.x); acc[0][0] = fma2(a2, b01, acc[0][0]); acc[0][1] = fma2(a2, b23, acc[0][1]);
            a2 = pack2(a.y, a.y); acc[1][0] = fma2(a2, b01, acc[1][0]); acc[1][1] = fma2(a2, b23, acc[1][1]);
            a2 = pack2(a.z, a.z); acc[2][0] = fma2(a2, b01, acc[2][0]); acc[2][1] = fma2(a2, b23, acc[2][1]);
            a2 = pack2(a.w, a.w); acc[3][0] = fma2(a2, b01, acc[3][0]); acc[3][1] = fma2(a2, b23, acc[3][1]);
        }
        __syncthreads();
    }

    const int col = n0 + tx * 4;
    const int h   = col >> 5;
    const int dd  = col & 31;
    const float f1x = fc1[h * HDIM + dd],     f1y = fc1[h * HDIM + dd + 1];
    const float f1z = fc1[h * HDIM + dd + 2], f1w = fc1[h * HDIM + dd + 3];
    const float f2x = fc2[h * HDIM + dd],     f2y = fc2[h * HDIM + dd + 1];
    const float f2z = fc2[h * HDIM + dd + 2], f2w = fc2[h * HDIM + dd + 3];

#pragma unroll
    for (int i = 0; i < 4; i++) {
        const int row = m0 + ty * 4 + i;
        float4 o;
        unpack2(acc[i][0], o.x, o.y);
        unpack2(acc[i][1], o.z, o.w);
        *(float4*)&out[row * OUT_DIM + col] = o;

        float s1 = o.x * f1x + o.y * f1y + o.z * f1z + o.w * f1w;
        float s2 = o.x * f2x + o.y * f2y + o.z * f2z + o.w * f2w;
#pragma unroll
        for (int off = 1; off < 8; off <<= 1) {
            s1 += __shfl_xor_sync(0xffffffffu, s1, off);
            s2 += __shfl_xor_sync(0xffffffffu, s2, off);
        }
        if ((tx & 7) == 0) {
            self_t [row * HEADS + h] = s1;
            neigh_t[row * HEADS + h] = s2;
        }
    }
}

// ---------------- Kernel 2: sparse softmax + aggregation, 4 rows/block ----------------
// exp(-1e9) underflows to 0 in fp32 so the dense-masked softmax equals the
// softmax over A's nonzeros (self-loop always present).
__global__ __launch_bounds__(256)
void attn_kernel(const float* __restrict__ A,
                 const float* __restrict__ inp,
                 const float* __restrict__ self_t, const float* __restrict__ neigh_t,
                 float* __restrict__ out) {
    __shared__ float sc[RPB][HEADS][SC_STR];   // ~20.6 KB
    __shared__ int   nbr[RPB][M_MAX];          // 2.5 KB (raw indices)
    __shared__ float s_self[RPB][HEADS];
    __shared__ float s_inv[RPB][HEADS];
    __shared__ int   s_cnt[RPB];

    const int blk  = blockIdx.x;
    const int row0 = blk * RPB;                 // global row of local row 0
    const int b    = row0 >> 10;                // same batch for all 4 rows
    const int t    = threadIdx.x;

    if (t < RPB) s_cnt[t] = 0;
    if (t < RPB * HEADS) s_self[t >> 3][t & 7] = self_t[(row0 + (t >> 3)) * HEADS + (t & 7)];
    __syncthreads();

    // ---- Phase 1: compact nonzeros of 4 rows of A (64 threads/row, 4 loads MLP) ----
    {
        const int r   = t >> 6;
        const int c64 = t & 63;
        const float4* Arow = (const float4*)(A + (long)(row0 + r) * NNODES);
        const float4 v0 = Arow[c64];
        const float4 v1 = Arow[c64 + 64];
        const float4 v2 = Arow[c64 + 128];
        const float4 v3 = Arow[c64 + 192];
        int idx[8]; int c = 0;
        const int b0 = c64 * 4;
        if (v0.x != 0.0f) idx[c++] = b0 + 0;
        if (v0.y != 0.0f) idx[c++] = b0 + 1;
        if (v0.z != 0.0f) idx[c++] = b0 + 2;
        if (v0.w != 0.0f) idx[c++] = b0 + 3;
        if (v1.x != 0.0f) idx[c++] = b0 + 256;
        if (v1.y != 0.0f) idx[c++] = b0 + 257;
        if (v1.z != 0.0f) idx[c++] = b0 + 258;
        if (v1.w != 0.0f) idx[c++] = b0 + 259;
        // second batch to keep idx[] small
        int idx2[8]; int c2 = 0;
        if (v2.x != 0.0f) idx2[c2++] = b0 + 512;
        if (v2.y != 0.0f) idx2[c2++] = b0 + 513;
        if (v2.z != 0.0f) idx2[c2++] = b0 + 514;
        if (v2.w != 0.0f) idx2[c2++] = b0 + 515;
        if (v3.x != 0.0f) idx2[c2++] = b0 + 768;
        if (v3.y != 0.0f) idx2[c2++] = b0 + 769;
        if (v3.z != 0.0f) idx2[c2++] = b0 + 770;
        if (v3.w != 0.0f) idx2[c2++] = b0 + 771;
        if (c + c2) {
            int p = atomicAdd(&s_cnt[r], c + c2);
            for (int i = 0; i < c; i++)  nbr[r][p + i] = idx[i];
            for (int i = 0; i < c2; i++) nbr[r][p + c + i] = idx2[i];
        }
    }
    __syncthreads();

    // ---- Phase 2: softmax weights. 32 (row,head) pairs over 8 warps ----
    {
        const int w = t >> 5, lane = t & 31;
        const float* nb = neigh_t + (long)b * NNODES * HEADS;
#pragma unroll
        for (int p = 0; p < 4; p++) {
            const int pair = w * 4 + p;
            const int pr = pair >> 3, ph = pair & 7;
            const int M = s_cnt[pr];
            const float sw = s_self[pr][ph];
            float mx = -1e30f;
            for (int j = lane; j < M; j += 32) {
                float s = sw + nb[nbr[pr][j] * HEADS + ph];
                s = (s > 0.0f) ? s : 0.01f * s;
                sc[pr][ph][j] = s;
                mx = fmaxf(mx, s);
            }
#pragma unroll
            for (int o = 16; o > 0; o >>= 1) mx = fmaxf(mx, __shfl_xor_sync(0xffffffffu, mx, o));
            float sum = 0.0f;
            for (int j = lane; j < M; j += 32) {
                float e = __expf(sc[pr][ph][j] - mx);
                sc[pr][ph][j] = e;
                sum += e;
            }
#pragma unroll
            for (int o = 16; o > 0; o >>= 1) sum += __shfl_xor_sync(0xffffffffu, sum, o);
            if (lane == 0) s_inv[pr][ph] = 1.0f / sum;
        }
    }
    __syncthreads();

    // ---- Phase 3: gather-aggregate. warp w -> (row w>>1, half w&1). Each warp
    // accumulates over ALL its row's neighbors privately (no cross-warp reduce).
    {
        const int w = t >> 5, lane = t & 31;
        const int r  = w >> 1;
        const int cq = (w & 1) * 32 + lane;      // float4 column 0..63
        const int h  = cq >> 3;                   // head of these 4 dims
        const int M  = s_cnt[r];
        const float* scr = sc[r][h];
        const int* nbrr = nbr[r];
        const float4* inpb = (const float4*)inp + (long)b * NNODES * (OUT_DIM / 4);

        float4 a0 = make_float4(0.f, 0.f, 0.f, 0.f);
        float4 a1 = make_float4(0.f, 0.f, 0.f, 0.f);
        float4 a2 = make_float4(0.f, 0.f, 0.f, 0.f);
        float4 a3 = make_float4(0.f, 0.f, 0.f, 0.f);
        int j = 0;
        for (; j + 3 < M; j += 4) {
            const int i0 = nbrr[j],     i1 = nbrr[j + 1];
            const int i2 = nbrr[j + 2], i3 = nbrr[j + 3];
            const float w0 = scr[j],     w1 = scr[j + 1];   // warp-broadcast LDS
            const float w2 = scr[j + 2], w3 = scr[j + 3];
            const float4 v0 = inpb[i0 * 64 + cq];
            const float4 v1 = inpb[i1 * 64 + cq];
            const float4 v2 = inpb[i2 * 64 + cq];
            const float4 v3 = inpb[i3 * 64 + cq];
            a0.x += w0 * v0.x; a0.y += w0 * v0.y; a0.z += w0 * v0.z; a0.w += w0 * v0.w;
            a1.x += w1 * v1.x; a1.y += w1 * v1.y; a1.z += w1 * v1.z; a1.w += w1 * v1.w;
            a2.x += w2 * v2.x; a2.y += w2 * v2.y; a2.z += w2 * v2.z; a2.w += w2 * v2.w;
            a3.x += w3 * v3.x; a3.y += w3 * v3.y; a3.z += w3 * v3.z; a3.w += w3 * v3.w;
        }
        for (; j < M; j++) {
            const int i0 = nbrr[j];
            const float w0 = scr[j];
            const float4 v0 = inpb[i0 * 64 + cq];
            a0.x += w0 * v0.x; a0.y += w0 * v0.y; a0.z += w0 * v0.z; a0.w += w0 * v0.w;
        }
        const float inv = s_inv[r][h];
        float4 o;
        o.x = fmaxf(((a0.x + a1.x) + (a2.x + a3.x)) * inv, 0.0f);
        o.y = fmaxf(((a0.y + a1.y) + (a2.y + a3.y)) * inv, 0.0f);
        o.z = fmaxf(((a0.z + a1.z) + (a2.z + a3.z)) * inv, 0.0f);
        o.w = fmaxf(((a0.w + a1.w) + (a2.w + a3.w)) * inv, 0.0f);
        *(float4*)&out[(long)(row0 + r) * OUT_DIM + cq * 4] = o;
    }
}

// ---------------- launch ----------------
extern "C" void kernel_launch(void* const* d_in, const int* in_sizes, int n_in,
                              void* d_out, int out_size) {
    const float* A   = (const float*)d_in[0];
    const float* X   = (const float*)d_in[1];
    const float* W   = (const float*)d_in[2];
    const float* fc1 = (const float*)d_in[3];
    const float* fc2 = (const float*)d_in[4];
    float* out = (float*)d_out;

    float *inp, *self_t, *neigh_t;
    cudaGetSymbolAddress((void**)&inp,     g_inputs);
    cudaGetSymbolAddress((void**)&self_t,  g_self);
    cudaGetSymbolAddress((void**)&neigh_t, g_neigh);

    dim3 ggrid(OUT_DIM / BN, ROWS / BM);   // (4, 128)
    gemm_kernel<<<ggrid, 256>>>(X, W, inp, self_t, neigh_t, fc1, fc2);
    attn_kernel<<<ROWS / RPB, 256>>>(A, inp, self_t, neigh_t, out);
}